// round 2
// baseline (speedup 1.0000x reference)
#include <cuda_runtime.h>
#include <cuda_bf16.h>
#include <cstdint>

// ---------------- Problem constants ----------------
#define N0 100000
#define N1 40000
#define N2 20000
#define N3 10000
#define E1 600000
#define E2 300000
#define E3 150000
#define C_IN 256   // feature width everywhere except final out
#define C_OUT 64

// ---------------- Scratch (device globals; no allocs allowed) ----------------
__device__ float g_mean[N1 * C_IN];          // reused per layer (max 40000x256)
__device__ float g_h1[N1 * C_IN];
__device__ float g_h2[N2 * C_IN];
__device__ int   g_deg[N1 + 1];
__device__ int   g_rowptr[N1 + 1];
__device__ int   g_cursor[N1];
__device__ int   g_col[E1];                  // reused per layer (max 600000)

// ---------------- Kernels ----------------
__global__ void zero_int_kernel(int* p, int n) {
    int i = blockIdx.x * blockDim.x + threadIdx.x;
    if (i < n) p[i] = 0;
}

__global__ void count_kernel(const int* __restrict__ dst, int* __restrict__ deg, int E) {
    int e = blockIdx.x * blockDim.x + threadIdx.x;
    if (e < E) atomicAdd(&deg[dst[e]], 1);
}

// single-block chunked exclusive scan: rowptr[0]=0, rowptr[i+1]=sum_{j<=i} deg[j]
__global__ void scan_kernel(const int* __restrict__ deg, int* __restrict__ rowptr, int n) {
    __shared__ int sh[1024];
    __shared__ int s_carry;
    int tid = threadIdx.x;
    if (tid == 0) { s_carry = 0; rowptr[0] = 0; }
    __syncthreads();
    for (int base = 0; base < n; base += 1024) {
        int i = base + tid;
        int v = (i < n) ? deg[i] : 0;
        sh[tid] = v;
        __syncthreads();
        #pragma unroll
        for (int off = 1; off < 1024; off <<= 1) {
            int t = (tid >= off) ? sh[tid - off] : 0;
            __syncthreads();
            sh[tid] += t;
            __syncthreads();
        }
        int carry = s_carry;
        if (i < n) rowptr[i + 1] = carry + sh[tid];
        __syncthreads();
        if (tid == 0) s_carry = carry + sh[1023];
        __syncthreads();
    }
}

__global__ void init_cursor_kernel(const int* __restrict__ rowptr, int* __restrict__ cursor, int n) {
    int i = blockIdx.x * blockDim.x + threadIdx.x;
    if (i < n) cursor[i] = rowptr[i];
}

__global__ void fill_kernel(const int* __restrict__ src, const int* __restrict__ dst,
                            int* __restrict__ cursor, int* __restrict__ col, int E) {
    int e = blockIdx.x * blockDim.x + threadIdx.x;
    if (e < E) {
        int pos = atomicAdd(&cursor[dst[e]], 1);
        col[pos] = src[e];
    }
}

// one warp per dst node: mean over in-neighbors, 256-wide rows via 2x float4 per lane
__global__ void aggregate_kernel(const float* __restrict__ xsrc,
                                 const int* __restrict__ rowptr,
                                 const int* __restrict__ col,
                                 float* __restrict__ mean, int nd) {
    int warp = (blockIdx.x * blockDim.x + threadIdx.x) >> 5;
    int lane = threadIdx.x & 31;
    if (warp >= nd) return;
    int beg = rowptr[warp], end = rowptr[warp + 1];
    float4 a0 = make_float4(0.f, 0.f, 0.f, 0.f);
    float4 a1 = make_float4(0.f, 0.f, 0.f, 0.f);
    for (int e = beg; e < end; ++e) {
        const float* row = xsrc + (size_t)col[e] * C_IN;
        float4 v0 = *(const float4*)(row + lane * 4);
        float4 v1 = *(const float4*)(row + 128 + lane * 4);
        a0.x += v0.x; a0.y += v0.y; a0.z += v0.z; a0.w += v0.w;
        a1.x += v1.x; a1.y += v1.y; a1.z += v1.z; a1.w += v1.w;
    }
    float inv = (end > beg) ? 1.0f / (float)(end - beg) : 0.0f;
    a0.x *= inv; a0.y *= inv; a0.z *= inv; a0.w *= inv;
    a1.x *= inv; a1.y *= inv; a1.z *= inv; a1.w *= inv;
    float* o = mean + (size_t)warp * C_IN;
    *(float4*)(o + lane * 4) = a0;
    *(float4*)(o + 128 + lane * 4) = a1;
}

// C[M,N] = act( A1@W1 + A2@W2 + bias ), A* are [M,256] row-major, W* are [256,N] row-major
#define BM 64
#define BN 64
#define BK 32
__global__ void gemm_fused_kernel(const float* __restrict__ A1, const float* __restrict__ A2,
                                  const float* __restrict__ W1, const float* __restrict__ W2,
                                  const float* __restrict__ bias, float* __restrict__ C,
                                  int M, int N, int do_relu) {
    __shared__ float As[BM][BK];
    __shared__ float Bs[BK][BN];
    int tid = threadIdx.x;          // 256 threads
    int tx = tid & 15;              // 0..15
    int ty = tid >> 4;              // 0..15
    int row0 = blockIdx.y * BM;
    int col0 = blockIdx.x * BN;
    float acc[4][4];
    #pragma unroll
    for (int i = 0; i < 4; i++)
        #pragma unroll
        for (int j = 0; j < 4; j++) acc[i][j] = 0.f;

    #pragma unroll
    for (int seg = 0; seg < 2; ++seg) {
        const float* A = seg ? A2 : A1;
        const float* W = seg ? W2 : W1;
        for (int k0 = 0; k0 < 256; k0 += BK) {
            // A tile: 64 rows x 32 k, 512 float4 slots
            #pragma unroll
            for (int i = 0; i < 2; ++i) {
                int s = tid + i * 256;
                int r = s >> 3;
                int kc = (s & 7) << 2;
                float4 v = make_float4(0.f, 0.f, 0.f, 0.f);
                int gr = row0 + r;
                if (gr < M) v = *(const float4*)(A + (size_t)gr * 256 + k0 + kc);
                *(float4*)&As[r][kc] = v;
            }
            // B tile: 32 k x 64 n
            #pragma unroll
            for (int i = 0; i < 2; ++i) {
                int s = tid + i * 256;
                int r = s >> 4;
                int nc = (s & 15) << 2;
                float4 v = *(const float4*)(W + (size_t)(k0 + r) * N + col0 + nc);
                *(float4*)&Bs[r][nc] = v;
            }
            __syncthreads();
            #pragma unroll
            for (int k = 0; k < BK; ++k) {
                float av[4], bv[4];
                #pragma unroll
                for (int i = 0; i < 4; i++) av[i] = As[ty * 4 + i][k];
                float4 b = *(const float4*)&Bs[k][tx * 4];
                bv[0] = b.x; bv[1] = b.y; bv[2] = b.z; bv[3] = b.w;
                #pragma unroll
                for (int i = 0; i < 4; i++)
                    #pragma unroll
                    for (int j = 0; j < 4; j++)
                        acc[i][j] += av[i] * bv[j];
            }
            __syncthreads();
        }
    }
    #pragma unroll
    for (int i = 0; i < 4; i++) {
        int gr = row0 + ty * 4 + i;
        if (gr >= M) continue;
        #pragma unroll
        for (int j = 0; j < 4; j++) {
            int gc = col0 + tx * 4 + j;
            float v = acc[i][j] + bias[gc];
            if (do_relu) v = fmaxf(v, 0.0f);
            C[(size_t)gr * N + gc] = v;
        }
    }
}

// ---------------- Host orchestration ----------------
static inline int cdiv(int a, int b) { return (a + b - 1) / b; }

static void build_csr_and_aggregate(const float* xsrc, const int* ei, int E, int nd,
                                    int* p_deg, int* p_rowptr, int* p_cursor, int* p_col,
                                    float* p_mean) {
    const int* src = ei;
    const int* dst = ei + E;
    zero_int_kernel<<<cdiv(nd, 256), 256>>>(p_deg, nd);
    count_kernel<<<cdiv(E, 256), 256>>>(dst, p_deg, E);
    scan_kernel<<<1, 1024>>>(p_deg, p_rowptr, nd);
    init_cursor_kernel<<<cdiv(nd, 256), 256>>>(p_rowptr, p_cursor, nd);
    fill_kernel<<<cdiv(E, 256), 256>>>(src, dst, p_cursor, p_col, E);
    aggregate_kernel<<<cdiv(nd * 32, 256), 256>>>(xsrc, p_rowptr, p_col, p_mean, nd);
}

extern "C" void kernel_launch(void* const* d_in, const int* in_sizes, int n_in,
                              void* d_out, int out_size) {
    const float* x   = (const float*)d_in[0];
    const int*   ei1 = (const int*)d_in[1];
    const int*   ei2 = (const int*)d_in[2];
    const int*   ei3 = (const int*)d_in[3];
    const float* Wl1 = (const float*)d_in[4];
    const float* bl1 = (const float*)d_in[5];
    const float* Wr1 = (const float*)d_in[6];
    const float* Wl2 = (const float*)d_in[7];
    const float* bl2 = (const float*)d_in[8];
    const float* Wr2 = (const float*)d_in[9];
    const float* Wl3 = (const float*)d_in[10];
    const float* bl3 = (const float*)d_in[11];
    const float* Wr3 = (const float*)d_in[12];
    const float* Wls = (const float*)d_in[13];
    const float* bls = (const float*)d_in[14];
    const float* Wrs = (const float*)d_in[15];
    float* out = (float*)d_out;

    float *p_mean, *p_h1, *p_h2;
    int *p_deg, *p_rowptr, *p_cursor, *p_col;
    cudaGetSymbolAddress((void**)&p_mean,   g_mean);
    cudaGetSymbolAddress((void**)&p_h1,     g_h1);
    cudaGetSymbolAddress((void**)&p_h2,     g_h2);
    cudaGetSymbolAddress((void**)&p_deg,    g_deg);
    cudaGetSymbolAddress((void**)&p_rowptr, g_rowptr);
    cudaGetSymbolAddress((void**)&p_cursor, g_cursor);
    cudaGetSymbolAddress((void**)&p_col,    g_col);

    // ---- Layer 1: x -> h1 [40000, 256], relu ----
    build_csr_and_aggregate(x, ei1, E1, N1, p_deg, p_rowptr, p_cursor, p_col, p_mean);
    {
        dim3 grid(256 / BN, cdiv(N1, BM));
        gemm_fused_kernel<<<grid, 256>>>(p_mean, x, Wl1, Wr1, bl1, p_h1, N1, 256, 1);
    }

    // ---- Layer 2: h1 -> h2 [20000, 256], relu ----
    build_csr_and_aggregate(p_h1, ei2, E2, N2, p_deg, p_rowptr, p_cursor, p_col, p_mean);
    {
        dim3 grid(256 / BN, cdiv(N2, BM));
        gemm_fused_kernel<<<grid, 256>>>(p_mean, p_h1, Wl2, Wr2, bl2, p_h2, N2, 256, 1);
    }

    // ---- Layer 3: h2 -> (mu, logstd) [10000, 64] each; shared aggregation ----
    build_csr_and_aggregate(p_h2, ei3, E3, N3, p_deg, p_rowptr, p_cursor, p_col, p_mean);
    {
        dim3 grid(C_OUT / BN, cdiv(N3, BM));
        gemm_fused_kernel<<<grid, 256>>>(p_mean, p_h2, Wl3, Wr3, bl3, out,              N3, C_OUT, 0);
        gemm_fused_kernel<<<grid, 256>>>(p_mean, p_h2, Wls, Wrs, bls, out + N3 * C_OUT, N3, C_OUT, 0);
    }
}

// round 4
// speedup vs baseline: 1.5056x; 1.5056x over previous
#include <cuda_runtime.h>
#include <cuda_bf16.h>
#include <cstdint>

// ---------------- Problem constants ----------------
#define N0 100000
#define N1 40000
#define N2 20000
#define N3 10000
#define E1 600000
#define E2 300000
#define E3 150000

// ---------------- Scratch (device globals; no allocs allowed) ----------------
__device__ __nv_bfloat16 g_Ahi[(size_t)N1 * 512];
__device__ __nv_bfloat16 g_Alo[(size_t)N1 * 512];
__device__ __nv_bfloat16 g_Whi[256 * 512];
__device__ __nv_bfloat16 g_Wlo[256 * 512];
__device__ float g_bias[256];
__device__ float g_h1[(size_t)N1 * 256];
__device__ float g_h2[(size_t)N2 * 256];
__device__ int   g_deg[N1 + 1];
__device__ int   g_rowptr[N1 + 1];
__device__ int   g_cursor[N1];
__device__ int   g_col[E1];

// ---------------- small helpers ----------------
__device__ __forceinline__ uint2 pack_hi4(const float* f, float* resid) {
    unsigned short s[4];
    #pragma unroll
    for (int j = 0; j < 4; j++) {
        __nv_bfloat16 h = __float2bfloat16(f[j]);
        s[j] = __bfloat16_as_ushort(h);
        resid[j] = f[j] - __bfloat162float(h);
    }
    uint2 u;
    u.x = (uint32_t)s[0] | ((uint32_t)s[1] << 16);
    u.y = (uint32_t)s[2] | ((uint32_t)s[3] << 16);
    return u;
}
__device__ __forceinline__ uint2 pack_bf4(const float* f) {
    unsigned short s[4];
    #pragma unroll
    for (int j = 0; j < 4; j++) s[j] = __bfloat16_as_ushort(__float2bfloat16(f[j]));
    uint2 u;
    u.x = (uint32_t)s[0] | ((uint32_t)s[1] << 16);
    u.y = (uint32_t)s[2] | ((uint32_t)s[3] << 16);
    return u;
}
__device__ __forceinline__ uint32_t smem_u32(const void* p) {
    uint32_t a;
    asm("{ .reg .u64 t; cvta.to.shared.u64 t, %1; cvt.u32.u64 %0, t; }" : "=r"(a) : "l"(p));
    return a;
}
__device__ __forceinline__ void cp16(uint32_t dst, const void* src, int sz) {
    asm volatile("cp.async.cg.shared.global [%0], [%1], 16, %2;" :: "r"(dst), "l"(src), "r"(sz));
}
__device__ __forceinline__ void cp_commit() { asm volatile("cp.async.commit_group;"); }

__device__ __forceinline__ void mma16816(float c[4], const uint32_t a[4], uint32_t b0, uint32_t b1) {
    asm volatile(
        "mma.sync.aligned.m16n8k16.row.col.f32.bf16.bf16.f32 "
        "{%0,%1,%2,%3}, {%4,%5,%6,%7}, {%8,%9}, {%0,%1,%2,%3};"
        : "+f"(c[0]), "+f"(c[1]), "+f"(c[2]), "+f"(c[3])
        : "r"(a[0]), "r"(a[1]), "r"(a[2]), "r"(a[3]), "r"(b0), "r"(b1));
}

// ---------------- CSR build kernels ----------------
__global__ void zero_int_kernel(int* p, int n) {
    int i = blockIdx.x * blockDim.x + threadIdx.x;
    if (i < n) p[i] = 0;
}
__global__ void count_kernel(const int* __restrict__ dst, int* __restrict__ deg, int E) {
    int e = blockIdx.x * blockDim.x + threadIdx.x;
    if (e < E) atomicAdd(&deg[dst[e]], 1);
}
__global__ void scan_kernel(const int* __restrict__ deg, int* __restrict__ rowptr, int n) {
    __shared__ int sh[1024];
    __shared__ int s_carry;
    int tid = threadIdx.x;
    if (tid == 0) { s_carry = 0; rowptr[0] = 0; }
    __syncthreads();
    for (int base = 0; base < n; base += 1024) {
        int i = base + tid;
        int v = (i < n) ? deg[i] : 0;
        sh[tid] = v;
        __syncthreads();
        #pragma unroll
        for (int off = 1; off < 1024; off <<= 1) {
            int t = (tid >= off) ? sh[tid - off] : 0;
            __syncthreads();
            sh[tid] += t;
            __syncthreads();
        }
        int carry = s_carry;
        if (i < n) rowptr[i + 1] = carry + sh[tid];
        __syncthreads();
        if (tid == 0) s_carry = carry + sh[1023];
        __syncthreads();
    }
}
__global__ void init_cursor_kernel(const int* __restrict__ rowptr, int* __restrict__ cursor, int n) {
    int i = blockIdx.x * blockDim.x + threadIdx.x;
    if (i < n) cursor[i] = rowptr[i];
}
__global__ void fill_kernel(const int* __restrict__ src, const int* __restrict__ dst,
                            int* __restrict__ cursor, int* __restrict__ col, int E) {
    int e = blockIdx.x * blockDim.x + threadIdx.x;
    if (e < E) {
        int pos = atomicAdd(&cursor[dst[e]], 1);
        col[pos] = src[e];
    }
}

// ---------------- aggregate: mean of neighbor rows -> split-bf16 A[:, 0:256) ----------------
__global__ void aggregate_kernel(const float* __restrict__ xsrc,
                                 const int* __restrict__ rowptr,
                                 const int* __restrict__ col,
                                 __nv_bfloat16* __restrict__ Ahi,
                                 __nv_bfloat16* __restrict__ Alo, int nd) {
    int warp = (blockIdx.x * blockDim.x + threadIdx.x) >> 5;
    int lane = threadIdx.x & 31;
    if (warp >= nd) return;
    int beg = rowptr[warp], end = rowptr[warp + 1];
    float4 a0 = make_float4(0.f, 0.f, 0.f, 0.f);
    float4 a1 = make_float4(0.f, 0.f, 0.f, 0.f);
    for (int e = beg; e < end; ++e) {
        const float* row = xsrc + (size_t)col[e] * 256;
        float4 v0 = *(const float4*)(row + lane * 4);
        float4 v1 = *(const float4*)(row + 128 + lane * 4);
        a0.x += v0.x; a0.y += v0.y; a0.z += v0.z; a0.w += v0.w;
        a1.x += v1.x; a1.y += v1.y; a1.z += v1.z; a1.w += v1.w;
    }
    float inv = (end > beg) ? 1.0f / (float)(end - beg) : 0.0f;
    float f0[4] = {a0.x * inv, a0.y * inv, a0.z * inv, a0.w * inv};
    float f1[4] = {a1.x * inv, a1.y * inv, a1.z * inv, a1.w * inv};
    float r0[4], r1[4];
    uint2 h0 = pack_hi4(f0, r0);
    uint2 h1 = pack_hi4(f1, r1);
    uint2 l0 = pack_bf4(r0);
    uint2 l1 = pack_bf4(r1);
    size_t base = (size_t)warp * 512;
    *(uint2*)(Ahi + base + lane * 4) = h0;
    *(uint2*)(Ahi + base + 128 + lane * 4) = h1;
    *(uint2*)(Alo + base + lane * 4) = l0;
    *(uint2*)(Alo + base + 128 + lane * 4) = l1;
}

// ---------------- convert dst features fp32 -> split-bf16 A[:, 256:512) ----------------
__global__ void convert_dst_kernel(const float* __restrict__ xd,
                                   __nv_bfloat16* __restrict__ Ahi,
                                   __nv_bfloat16* __restrict__ Alo, int M) {
    int i = blockIdx.x * blockDim.x + threadIdx.x;
    if (i >= M * 64) return;
    int row = i >> 6;
    int c4 = (i & 63) * 4;
    float4 v = *(const float4*)(xd + (size_t)row * 256 + c4);
    float f[4] = {v.x, v.y, v.z, v.w};
    float r[4];
    uint2 h = pack_hi4(f, r);
    uint2 l = pack_bf4(r);
    size_t o = (size_t)row * 512 + 256 + c4;
    *(uint2*)(Ahi + o) = h;
    *(uint2*)(Alo + o) = l;
}

// ---------------- convert weights: [Wl;Wr] -> W^T split-bf16 [N,512] + merged bias ----------------
__global__ void convert_w_kernel(const float* __restrict__ Wl, const float* __restrict__ Wr,
                                 const float* __restrict__ bl,
                                 __nv_bfloat16* __restrict__ Whi, __nv_bfloat16* __restrict__ Wlo,
                                 float* __restrict__ bmerged, int nhead, int base) {
    int i = blockIdx.x * blockDim.x + threadIdx.x;
    if (i >= nhead * 512) return;
    int n = i >> 9, k = i & 511;
    float v = (k < 256) ? Wl[k * nhead + n] : Wr[(k - 256) * nhead + n];
    __nv_bfloat16 h = __float2bfloat16(v);
    float r = v - __bfloat162float(h);
    size_t o = (size_t)(base + n) * 512 + k;
    Whi[o] = h;
    Wlo[o] = __float2bfloat16(r);
    if (k == 0) bmerged[base + n] = bl[n];
}

// ---------------- mma.sync split-bf16 GEMM ----------------
// C[M,N] = act(A[M,512] @ W^T[N,512]^T + bias), A/W in hi+lo bf16 pairs.
// 3 tensor passes: Ah*Bh + Ah*Bl + Al*Bh. CTA tile 128x128, BK=32, 8 warps (32x64 each).
// mode 0: relu, row-major [M,N]. mode 1: split heads (cols<64 -> mu, >=64 -> logstd+N3*64).
#define TSTRIDE 40                 // padded bf16 row stride in SMEM
#define TILE_E  (128 * TSTRIDE)    // elements per tile (5120)
#define STAGE_E (4 * TILE_E)       // 4 tiles per stage (Ah, Al, Bh, Bl)
#define STAGE_B (STAGE_E * 2)      // bytes per stage (40960)
#define GEMM_SMEM (2 * STAGE_B)    // 81920

__global__ void __launch_bounds__(256) gemm_mma_kernel(
    const __nv_bfloat16* __restrict__ Ahi, const __nv_bfloat16* __restrict__ Alo,
    const __nv_bfloat16* __restrict__ Whi, const __nv_bfloat16* __restrict__ Wlo,
    const float* __restrict__ bias, float* __restrict__ out, int M, int N, int mode)
{
    extern __shared__ __nv_bfloat16 sm[];
    const uint32_t sb = smem_u32(sm);
    const int tid = threadIdx.x;
    const int wid = tid >> 5;
    const int lane = tid & 31;
    const int g = lane >> 2;       // 0..7
    const int t4 = lane & 3;       // 0..3
    const int wm = wid & 3;        // 4 row slices of 32
    const int wn = wid >> 2;       // 2 col slices of 64
    const int m0 = blockIdx.y * 128;
    const int n0 = blockIdx.x * 128;

    float acc[2][8][4];
    #pragma unroll
    for (int mt = 0; mt < 2; mt++)
        #pragma unroll
        for (int nt = 0; nt < 8; nt++)
            #pragma unroll
            for (int j = 0; j < 4; j++) acc[mt][nt][j] = 0.f;

    // prefetch lambda-ish: copy chunk `c` into stage `c&1`
    // per thread: 2 vectors (16B) per tile, 4 tiles
    auto prefetch = [&](int c) {
        const int ki = c * 32;
        const uint32_t stage = (uint32_t)(c & 1) * STAGE_B;
        #pragma unroll
        for (int t = 0; t < 2; t++) {
            int v = tid + t * 256;
            int r = v >> 2;
            int kc = (v & 3) * 8;
            uint32_t soff = stage + (uint32_t)(r * TSTRIDE + kc) * 2;
            // A tiles
            int gr = m0 + r;
            int ok = (gr < M) ? 16 : 0;
            size_t ao = (size_t)((gr < M) ? gr : 0) * 512 + ki + kc;
            cp16(sb + soff, Ahi + ao, ok);
            cp16(sb + soff + TILE_E * 2, Alo + ao, ok);
            // B tiles (always in-range: N multiple of 128, K full)
            size_t bo = (size_t)(n0 + r) * 512 + ki + kc;
            cp16(sb + soff + TILE_E * 4, Whi + bo, 16);
            cp16(sb + soff + TILE_E * 6, Wlo + bo, 16);
        }
        cp_commit();
    };

    prefetch(0);
    for (int c = 0; c < 16; ++c) {
        if (c + 1 < 16) {
            prefetch(c + 1);
            asm volatile("cp.async.wait_group 1;");
        } else {
            asm volatile("cp.async.wait_group 0;");
        }
        __syncthreads();
        const __nv_bfloat16* stg = sm + (size_t)(c & 1) * STAGE_E;
        #pragma unroll
        for (int p = 0; p < 3; p++) {
            const __nv_bfloat16* At = stg + ((p < 2) ? 0 : TILE_E);
            const __nv_bfloat16* Bt = stg + ((p == 1) ? 3 * TILE_E : 2 * TILE_E);
            #pragma unroll
            for (int kk = 0; kk < 32; kk += 16) {
                uint32_t a[2][4];
                #pragma unroll
                for (int mt = 0; mt < 2; mt++) {
                    const __nv_bfloat16* ap = At + (wm * 32 + mt * 16 + g) * TSTRIDE + kk + 2 * t4;
                    a[mt][0] = *(const uint32_t*)ap;
                    a[mt][1] = *(const uint32_t*)(ap + 8 * TSTRIDE);
                    a[mt][2] = *(const uint32_t*)(ap + 8);
                    a[mt][3] = *(const uint32_t*)(ap + 8 * TSTRIDE + 8);
                }
                #pragma unroll
                for (int nt = 0; nt < 8; nt++) {
                    const __nv_bfloat16* bp = Bt + (wn * 64 + nt * 8 + g) * TSTRIDE + kk + 2 * t4;
                    uint32_t b0 = *(const uint32_t*)bp;
                    uint32_t b1 = *(const uint32_t*)(bp + 8);
                    mma16816(acc[0][nt], a[0], b0, b1);
                    mma16816(acc[1][nt], a[1], b0, b1);
                }
            }
        }
        __syncthreads();
    }

    // epilogue
    #pragma unroll
    for (int mt = 0; mt < 2; mt++) {
        #pragma unroll
        for (int half = 0; half < 2; half++) {
            int row = m0 + wm * 32 + mt * 16 + g + half * 8;
            if (row >= M) continue;
            #pragma unroll
            for (int nt = 0; nt < 8; nt++) {
                int col = n0 + wn * 64 + nt * 8 + 2 * t4;
                float v0 = acc[mt][nt][half * 2 + 0] + __ldg(&bias[col]);
                float v1 = acc[mt][nt][half * 2 + 1] + __ldg(&bias[col + 1]);
                if (mode == 0) {
                    float2 o = make_float2(fmaxf(v0, 0.f), fmaxf(v1, 0.f));
                    *(float2*)(out + (size_t)row * N + col) = o;
                } else {
                    float* dst = (col < 64) ? (out + (size_t)row * 64 + col)
                                            : (out + (size_t)N3 * 64 + (size_t)row * 64 + (col - 64));
                    *(float2*)dst = make_float2(v0, v1);
                }
            }
        }
    }
}

// ---------------- Host orchestration ----------------
static inline int cdiv(int a, int b) { return (a + b - 1) / b; }

static void build_csr_and_aggregate(const float* xsrc, const int* ei, int E, int nd,
                                    int* p_deg, int* p_rowptr, int* p_cursor, int* p_col,
                                    __nv_bfloat16* p_Ahi, __nv_bfloat16* p_Alo) {
    const int* src = ei;
    const int* dst = ei + E;
    zero_int_kernel<<<cdiv(nd, 256), 256>>>(p_deg, nd);
    count_kernel<<<cdiv(E, 256), 256>>>(dst, p_deg, E);
    scan_kernel<<<1, 1024>>>(p_deg, p_rowptr, nd);
    init_cursor_kernel<<<cdiv(nd, 256), 256>>>(p_rowptr, p_cursor, nd);
    fill_kernel<<<cdiv(E, 256), 256>>>(src, dst, p_cursor, p_col, E);
    aggregate_kernel<<<cdiv(nd * 32, 256), 256>>>(xsrc, p_rowptr, p_col, p_Ahi, p_Alo, nd);
}

extern "C" void kernel_launch(void* const* d_in, const int* in_sizes, int n_in,
                              void* d_out, int out_size) {
    const float* x   = (const float*)d_in[0];
    const int*   ei1 = (const int*)d_in[1];
    const int*   ei2 = (const int*)d_in[2];
    const int*   ei3 = (const int*)d_in[3];
    const float* Wl1 = (const float*)d_in[4];
    const float* bl1 = (const float*)d_in[5];
    const float* Wr1 = (const float*)d_in[6];
    const float* Wl2 = (const float*)d_in[7];
    const float* bl2 = (const float*)d_in[8];
    const float* Wr2 = (const float*)d_in[9];
    const float* Wl3 = (const float*)d_in[10];
    const float* bl3 = (const float*)d_in[11];
    const float* Wr3 = (const float*)d_in[12];
    const float* Wls = (const float*)d_in[13];
    const float* bls = (const float*)d_in[14];
    const float* Wrs = (const float*)d_in[15];
    float* out = (float*)d_out;

    __nv_bfloat16 *p_Ahi, *p_Alo, *p_Whi, *p_Wlo;
    float *p_bias, *p_h1, *p_h2;
    int *p_deg, *p_rowptr, *p_cursor, *p_col;
    cudaGetSymbolAddress((void**)&p_Ahi,    g_Ahi);
    cudaGetSymbolAddress((void**)&p_Alo,    g_Alo);
    cudaGetSymbolAddress((void**)&p_Whi,    g_Whi);
    cudaGetSymbolAddress((void**)&p_Wlo,    g_Wlo);
    cudaGetSymbolAddress((void**)&p_bias,   g_bias);
    cudaGetSymbolAddress((void**)&p_h1,     g_h1);
    cudaGetSymbolAddress((void**)&p_h2,     g_h2);
    cudaGetSymbolAddress((void**)&p_deg,    g_deg);
    cudaGetSymbolAddress((void**)&p_rowptr, g_rowptr);
    cudaGetSymbolAddress((void**)&p_cursor, g_cursor);
    cudaGetSymbolAddress((void**)&p_col,    g_col);

    cudaFuncSetAttribute(gemm_mma_kernel, cudaFuncAttributeMaxDynamicSharedMemorySize, GEMM_SMEM);

    // ---- Layer 1: x -> h1 [40000, 256], relu ----
    build_csr_and_aggregate(x, ei1, E1, N1, p_deg, p_rowptr, p_cursor, p_col, p_Ahi, p_Alo);
    convert_dst_kernel<<<cdiv(N1 * 64, 256), 256>>>(x, p_Ahi, p_Alo, N1);
    convert_w_kernel<<<cdiv(256 * 512, 256), 256>>>(Wl1, Wr1, bl1, p_Whi, p_Wlo, p_bias, 256, 0);
    {
        dim3 grid(2, cdiv(N1, 128));
        gemm_mma_kernel<<<grid, 256, GEMM_SMEM>>>(p_Ahi, p_Alo, p_Whi, p_Wlo, p_bias, p_h1, N1, 256, 0);
    }

    // ---- Layer 2: h1 -> h2 [20000, 256], relu ----
    build_csr_and_aggregate(p_h1, ei2, E2, N2, p_deg, p_rowptr, p_cursor, p_col, p_Ahi, p_Alo);
    convert_dst_kernel<<<cdiv(N2 * 64, 256), 256>>>(p_h1, p_Ahi, p_Alo, N2);
    convert_w_kernel<<<cdiv(256 * 512, 256), 256>>>(Wl2, Wr2, bl2, p_Whi, p_Wlo, p_bias, 256, 0);
    {
        dim3 grid(2, cdiv(N2, 128));
        gemm_mma_kernel<<<grid, 256, GEMM_SMEM>>>(p_Ahi, p_Alo, p_Whi, p_Wlo, p_bias, p_h2, N2, 256, 0);
    }

    // ---- Layer 3: h2 -> (mu | logstd) [10000, 64] each; merged N=128 GEMM ----
    build_csr_and_aggregate(p_h2, ei3, E3, N3, p_deg, p_rowptr, p_cursor, p_col, p_Ahi, p_Alo);
    convert_dst_kernel<<<cdiv(N3 * 64, 256), 256>>>(p_h2, p_Ahi, p_Alo, N3);
    convert_w_kernel<<<cdiv(64 * 512, 256), 256>>>(Wl3, Wr3, bl3, p_Whi, p_Wlo, p_bias, 64, 0);
    convert_w_kernel<<<cdiv(64 * 512, 256), 256>>>(Wls, Wrs, bls, p_Whi, p_Wlo, p_bias, 64, 64);
    {
        dim3 grid(1, cdiv(N3, 128));
        gemm_mma_kernel<<<grid, 256, GEMM_SMEM>>>(p_Ahi, p_Alo, p_Whi, p_Wlo, p_bias, out, N3, 128, 1);
    }
}